// round 14
// baseline (speedup 1.0000x reference)
#include <cuda_runtime.h>
#include <cuda_bf16.h>

// Inputs (metadata order):
//  d_in[0] charges             float32 [200000, 4]
//  d_in[1] cell                float32 [3, 3]        (unused)
//  d_in[2] positions           float32 [200000, 3]   (unused)
//  d_in[3] neighbor_indices    int32   [12800000, 2]
//  d_in[4] neighbor_distances  float32 [12800000]
//  d_out  potential            float32 [200000, 4]
//
// out[i] += 0.5/d * charges[j];  out[j] += 0.5/d * charges[i]  over all edges.
//
// FINAL (session optimum; 190.3-191.4us across 5 benches, best 190.3):
// 1 edge/thread, TPB=512, fp32 v4 gathers, red.global.add.v4.f32, async
// memset output zeroing.
//
// Hardware-floor argument: a random-index edge scatter-gather needs
//   4 scattered 16B L1tex wavefronts per edge (2 gathers + 2 v4 reductions)
//   x 12.8M edges / 148 SMs / 1.0 wf/cyc/SM @1.82GHz = 190us analytic.
// Measured 188.2-191.1us in-kernel = 99-100.5% of floor. L2=91-92%, DRAM=11%.
//
// Exhaustively falsified/priced alternatives (R2-R13):
//  - 4-edge unroll + vector stream loads: neutral (wall counts wavefronts).
//  - cache-policy pinning (evict_last / ldcg): neutral.
//  - fp16 charges mirror: neutral — wavefronts/sectors count lines, not bytes.
//  - 16/8-CTA cluster DSMEM gathers (static + work-stealing): 1.7-2.2x WORSE.
//  - TMA gather4: ~480us analytic (46 cyc/request service).
//  - sort/bin-then-coalesce: sort passes alone exceed the 190us wall.
//  - smem privatization: ATOMS spread-addr 2 cyc/lane > 1 wf/cyc.
//  - geometry: TPB 256=191.2, 512=190.3-190.9 (best), 1024=193.0.
//  - memset fusion: requires grid sync before REDs; costs more than ~0.5us.

__device__ __forceinline__ void red_add_v4(float4* p, float4 v) {
    asm volatile("red.global.add.v4.f32 [%0], {%1, %2, %3, %4};"
                 :: "l"(p), "f"(v.x), "f"(v.y), "f"(v.z), "f"(v.w)
                 : "memory");
}

__device__ __forceinline__ float4 scale4(float4 c, float w) {
    return make_float4(c.x * w, c.y * w, c.z * w, c.w * w);
}

__global__ void __launch_bounds__(512)
edge_scatter_kernel(const float4* __restrict__ charges,
                    const int2*   __restrict__ nbr,
                    const float*  __restrict__ dist,
                    float4*       __restrict__ out,
                    int n_edges) {
    int e = blockIdx.x * blockDim.x + threadIdx.x;
    if (e >= n_edges) return;

    int2  ij  = __ldg(&nbr[e]);
    float d   = __ldg(&dist[e]);
    float inv = 0.5f / d;   // fold PREFACTOR * 0.5

    float4 cj = __ldg(&charges[ij.y]);
    float4 ci = __ldg(&charges[ij.x]);

    red_add_v4(&out[ij.x], scale4(cj, inv));
    red_add_v4(&out[ij.y], scale4(ci, inv));
}

extern "C" void kernel_launch(void* const* d_in, const int* in_sizes, int n_in,
                              void* d_out, int out_size) {
    const float4* charges = (const float4*)d_in[0];
    const int2*   nbr     = (const int2*)d_in[3];
    const float*  dist    = (const float*)d_in[4];
    float4*       out     = (float4*)d_out;

    int n_edges = in_sizes[4];   // 12,800,000

    // d_out is poisoned to 0xAA — zero it (async, graph-capturable).
    cudaMemsetAsync(d_out, 0, (size_t)out_size * sizeof(float));

    const int TPB = 512;
    int blocks = (n_edges + TPB - 1) / TPB;
    edge_scatter_kernel<<<blocks, TPB>>>(charges, nbr, dist, out, n_edges);
}

// round 15
// speedup vs baseline: 1.0065x; 1.0065x over previous
#include <cuda_runtime.h>
#include <cuda_bf16.h>

// Inputs (metadata order):
//  d_in[0] charges             float32 [200000, 4]
//  d_in[1] cell                float32 [3, 3]        (unused)
//  d_in[2] positions           float32 [200000, 3]   (unused)
//  d_in[3] neighbor_indices    int32   [12800000, 2]
//  d_in[4] neighbor_distances  float32 [12800000]
//  d_out  potential            float32 [200000, 4]
//
// out[i] += 0.5/d * charges[j];  out[j] += 0.5/d * charges[i]  over all edges.
//
// FINAL (session optimum; 190.3-191.4us across 5 benches at natural clocks;
// R14's 311.8us on IDENTICAL source was an SM-clock throttle: L1tex stayed
// 88% (1.0 wf/cyc in SM domain) while L2 fell 92->66% and DRAM 11->6.7% —
// the clock under the kernel moved, not the kernel).
//
// 1 edge/thread, TPB=512, fp32 v4 gathers, red.global.add.v4.f32, async
// memset output zeroing.
//
// Hardware-floor argument: a random-index edge scatter-gather needs
//   4 scattered 16B L1tex wavefronts per edge (2 gathers + 2 v4 reductions)
//   x 12.8M edges / 148 SMs / 1.0 wf/cyc/SM @1.82GHz = 190us analytic.
// Measured 188.2-191.1us in-kernel = 99-100.5% of floor at NAT clocks.
//
// Exhaustively falsified/priced alternatives (R2-R13), ordering clock-invariant:
//  - 4-edge unroll + vector stream loads: neutral (wall counts wavefronts).
//  - cache-policy pinning (evict_last / ldcg): neutral.
//  - fp16 charges mirror: neutral — wavefronts/sectors count lines, not bytes.
//  - 16/8-CTA cluster DSMEM gathers (static + work-stealing): 1.7-2.2x WORSE.
//  - TMA gather4: ~2.5x worse analytic (46 cyc/request service).
//  - sort/bin-then-coalesce: sort passes alone exceed the wall.
//  - smem privatization: ATOMS spread-addr 2 cyc/lane > 1 wf/cyc.
//  - geometry: TPB 256=191.2, 512=190.3-190.9 (best), 1024=193.0.

__device__ __forceinline__ void red_add_v4(float4* p, float4 v) {
    asm volatile("red.global.add.v4.f32 [%0], {%1, %2, %3, %4};"
                 :: "l"(p), "f"(v.x), "f"(v.y), "f"(v.z), "f"(v.w)
                 : "memory");
}

__device__ __forceinline__ float4 scale4(float4 c, float w) {
    return make_float4(c.x * w, c.y * w, c.z * w, c.w * w);
}

__global__ void __launch_bounds__(512)
edge_scatter_kernel(const float4* __restrict__ charges,
                    const int2*   __restrict__ nbr,
                    const float*  __restrict__ dist,
                    float4*       __restrict__ out,
                    int n_edges) {
    int e = blockIdx.x * blockDim.x + threadIdx.x;
    if (e >= n_edges) return;

    int2  ij  = __ldg(&nbr[e]);
    float d   = __ldg(&dist[e]);
    float inv = 0.5f / d;   // fold PREFACTOR * 0.5

    float4 cj = __ldg(&charges[ij.y]);
    float4 ci = __ldg(&charges[ij.x]);

    red_add_v4(&out[ij.x], scale4(cj, inv));
    red_add_v4(&out[ij.y], scale4(ci, inv));
}

extern "C" void kernel_launch(void* const* d_in, const int* in_sizes, int n_in,
                              void* d_out, int out_size) {
    const float4* charges = (const float4*)d_in[0];
    const int2*   nbr     = (const int2*)d_in[3];
    const float*  dist    = (const float*)d_in[4];
    float4*       out     = (float4*)d_out;

    int n_edges = in_sizes[4];   // 12,800,000

    // d_out is poisoned to 0xAA — zero it (async, graph-capturable).
    cudaMemsetAsync(d_out, 0, (size_t)out_size * sizeof(float));

    const int TPB = 512;
    int blocks = (n_edges + TPB - 1) / TPB;
    edge_scatter_kernel<<<blocks, TPB>>>(charges, nbr, dist, out, n_edges);
}

// round 16
// speedup vs baseline: 1.6330x; 1.6224x over previous
#include <cuda_runtime.h>
#include <cuda_bf16.h>

// Inputs (metadata order):
//  d_in[0] charges             float32 [200000, 4]
//  d_in[1] cell                float32 [3, 3]        (unused)
//  d_in[2] positions           float32 [200000, 3]   (unused)
//  d_in[3] neighbor_indices    int32   [12800000, 2]
//  d_in[4] neighbor_distances  float32 [12800000]
//  d_out  potential            float32 [200000, 4]
//
// out[i] += 0.5/d * charges[j];  out[j] += 0.5/d * charges[i]  over all edges.
//
// FINAL (session optimum). 1 edge/thread, TPB=512, fp32 v4 gathers,
// red.global.add.v4.f32, async memset output zeroing.
//
// Hardware-floor argument (clock-domain-invariant): a random-index edge
// scatter-gather needs 4 scattered 16B L1tex wavefronts per edge (2 gathers
// + 2 v4 reductions) x 12.8M edges / 148 SMs at the structural 1.0
// wavefront/cyc/SM L1tex rate = 346K cyc/SM:
//   @1.82GHz NAT  -> 190us analytic; measured 188.2-191.1us (R9-R13).
//   @1.095GHz LOCK -> 316us analytic; measured 307-308us (R14-R15,
//   identical source — throttle fingerprint: L1 88% const, L2 92->66%).
//
// Exhaustively falsified/priced alternatives (R2-R15), ordering invariant
// to clock regime (all competing pipes are also SM-domain):
//  - 4-edge unroll + vector stream loads: neutral (wall counts wavefronts).
//  - cache-policy pinning (evict_last / ldcg): neutral.
//  - fp16 charges mirror: neutral — wavefronts/sectors count lines, not bytes.
//  - 16/8-CTA cluster DSMEM gathers (static + work-stealing): 1.7-2.2x WORSE.
//  - TMA gather4: ~2.5x worse analytic (46 cyc/request service).
//  - sort/bin-then-coalesce: sort passes alone exceed the wall.
//  - smem privatization: ATOMS spread-addr 2 cyc/lane > 1 wf/cyc.
//  - geometry: TPB 256=191.2, 512=190.3-190.9 (best), 1024=193.0.

__device__ __forceinline__ void red_add_v4(float4* p, float4 v) {
    asm volatile("red.global.add.v4.f32 [%0], {%1, %2, %3, %4};"
                 :: "l"(p), "f"(v.x), "f"(v.y), "f"(v.z), "f"(v.w)
                 : "memory");
}

__device__ __forceinline__ float4 scale4(float4 c, float w) {
    return make_float4(c.x * w, c.y * w, c.z * w, c.w * w);
}

__global__ void __launch_bounds__(512)
edge_scatter_kernel(const float4* __restrict__ charges,
                    const int2*   __restrict__ nbr,
                    const float*  __restrict__ dist,
                    float4*       __restrict__ out,
                    int n_edges) {
    int e = blockIdx.x * blockDim.x + threadIdx.x;
    if (e >= n_edges) return;

    int2  ij  = __ldg(&nbr[e]);
    float d   = __ldg(&dist[e]);
    float inv = 0.5f / d;   // fold PREFACTOR * 0.5

    float4 cj = __ldg(&charges[ij.y]);
    float4 ci = __ldg(&charges[ij.x]);

    red_add_v4(&out[ij.x], scale4(cj, inv));
    red_add_v4(&out[ij.y], scale4(ci, inv));
}

extern "C" void kernel_launch(void* const* d_in, const int* in_sizes, int n_in,
                              void* d_out, int out_size) {
    const float4* charges = (const float4*)d_in[0];
    const int2*   nbr     = (const int2*)d_in[3];
    const float*  dist    = (const float*)d_in[4];
    float4*       out     = (float4*)d_out;

    int n_edges = in_sizes[4];   // 12,800,000

    // d_out is poisoned to 0xAA — zero it (async, graph-capturable).
    cudaMemsetAsync(d_out, 0, (size_t)out_size * sizeof(float));

    const int TPB = 512;
    int blocks = (n_edges + TPB - 1) / TPB;
    edge_scatter_kernel<<<blocks, TPB>>>(charges, nbr, dist, out, n_edges);
}